// round 3
// baseline (speedup 1.0000x reference)
#include <cuda_runtime.h>
#include <math_constants.h>

// Roi_61564061221098: quantized RoI max pooling.
// x: (4, 512, 50, 68) f32, rois: (2000, 4) f32 [y1,x1,y2,x2], roi_indices: (2000,) i32
// out: (2000, 512*7*7) f32
//
// One warp per (roi, channel). Lanes sweep the roi's W-span coalesced,
// compute per-column maxes over each ph h-bin, then 7 lanes do the per-pw
// segmented reduce in shared memory.
//
// Bin math replicates XLA's semantics bit-exactly:
//   - XLA rewrites x / 7.0 into x * fl(1/7)  (divide-by-constant -> multiply
//     by reciprocal). We must do the same or bin boundaries flip (e.g.
//     roi_w = 21: true division gives bin_w = 3.0, recip-mul gives 3.0000002,
//     shifting every ceil() by +1).
//   - all other ops via _rn intrinsics (immune to fast-math flags).

#define NC   512
#define FH   50
#define FW   68
#define PP   7
#define SCALE 0.0625f
#define NEG_INF (-CUDART_INF_F)

__global__ __launch_bounds__(256, 6)
void roi_maxpool_kernel(const float* __restrict__ x,
                        const float* __restrict__ rois,
                        const int*   __restrict__ roi_idx,
                        float* __restrict__ out,
                        int R)
{
    const int r    = blockIdx.x;
    const int warp = threadIdx.x >> 5;
    const int lane = threadIdx.x & 31;
    const int c    = blockIdx.y * 8 + warp;   // 64 * 8 = 512 channels

    if (r >= R) return;

    // ---- per-roi bin computation (XLA-exact fp32, uniform across warp) ----
    // reference permutation: boxes = [x1, y1, x2, y2] from rois=[y1,x1,y2,x2]
    const float y1 = rois[r * 4 + 0];
    const float x1 = rois[r * 4 + 1];
    const float y2 = rois[r * 4 + 2];
    const float x2 = rois[r * 4 + 3];
    const float rb0 = rintf(__fmul_rn(x1, SCALE));   // x start (round half even)
    const float rb1 = rintf(__fmul_rn(y1, SCALE));   // y start
    const float rb2 = rintf(__fmul_rn(x2, SCALE));   // x end
    const float rb3 = rintf(__fmul_rn(y2, SCALE));   // y end
    const float roiw = fmaxf(__fadd_rn(__fsub_rn(rb2, rb0), 1.0f), 1.0f);
    const float roih = fmaxf(__fadd_rn(__fsub_rn(rb3, rb1), 1.0f), 1.0f);
    // XLA: divide-by-constant -> multiply by (exactly rounded) reciprocal.
    const float RECIP7 = (float)(1.0 / 7.0);         // fl(1/7) = 0.142857149...
    const float bw = __fmul_rn(roiw, RECIP7);
    const float bh = __fmul_rn(roih, RECIP7);

    int hs[PP], he[PP], ws[PP], we[PP];
#pragma unroll
    for (int p = 0; p < PP; p++) {
        const float fp  = (float)p;
        const float fp1 = (float)(p + 1);
        hs[p] = (int)fminf(fmaxf(__fadd_rn(floorf(__fmul_rn(fp,  bh)), rb1), 0.0f), (float)FH);
        he[p] = (int)fminf(fmaxf(__fadd_rn(ceilf (__fmul_rn(fp1, bh)), rb1), 0.0f), (float)FH);
        ws[p] = (int)fminf(fmaxf(__fadd_rn(floorf(__fmul_rn(fp,  bw)), rb0), 0.0f), (float)FW);
        we[p] = (int)fminf(fmaxf(__fadd_rn(ceilf (__fmul_rn(fp1, bw)), rb0), 0.0f), (float)FW);
    }
    const int w0   = ws[0];
    const int span = we[PP - 1] - w0;   // <= 68

    const int n = roi_idx[r];
    const float* __restrict__ fm = x + ((long long)n * NC + c) * (FH * FW);

    __shared__ float scol[8][96];   // per-warp column maxes (span <= 68, slack for unguarded stores)
    __shared__ float sout[8][52];   // per-warp 49 outputs

    const bool a0 = (lane      < span);
    const bool a1 = (lane + 32 < span);
    const bool a2 = (lane + 64 < span);

#pragma unroll
    for (int ph = 0; ph < PP; ph++) {
        float m0 = NEG_INF, m1 = NEG_INF, m2 = NEG_INF;
        const int h0 = hs[ph], h1 = he[ph];
        for (int h = h0; h < h1; h++) {
            const float* __restrict__ row = fm + h * FW + w0;
            if (a0) m0 = fmaxf(m0, __ldg(row + lane));
            if (a1) m1 = fmaxf(m1, __ldg(row + lane + 32));
            if (a2) m2 = fmaxf(m2, __ldg(row + lane + 64));
        }
        scol[warp][lane]      = m0;
        scol[warp][lane + 32] = m1;
        scol[warp][lane + 64] = m2;
        __syncwarp();
        if (lane < PP) {
            float m = NEG_INF;
            const int j0 = ws[lane] - w0;
            const int j1 = we[lane] - w0;
            for (int j = j0; j < j1; j++) m = fmaxf(m, scol[warp][j]);
            // empty bin (or all -inf) -> 0.0 per reference's isfinite rule
            sout[warp][ph * PP + lane] = (m == NEG_INF) ? 0.0f : m;
        }
        __syncwarp();
    }

    // ---- contiguous 49-float output burst per warp ----
    const long long obase = (long long)r * (NC * PP * PP) + (long long)c * (PP * PP);
    out[obase + lane] = sout[warp][lane];
    if (lane < 17) out[obase + 32 + lane] = sout[warp][32 + lane];
}

extern "C" void kernel_launch(void* const* d_in, const int* in_sizes, int n_in,
                              void* d_out, int out_size)
{
    const float* x    = (const float*)d_in[0];
    const float* rois = (const float*)d_in[1];
    const int*   ridx = (const int*)d_in[2];
    float*       out  = (float*)d_out;
    const int R = in_sizes[2];

    dim3 grid(R, NC / 8);
    roi_maxpool_kernel<<<grid, 256>>>(x, rois, ridx, out, R);
}

// round 4
// speedup vs baseline: 3.5676x; 3.5676x over previous
#include <cuda_runtime.h>
#include <math_constants.h>

// Roi_61564061221098: quantized RoI max pooling, round 4.
// x: (4, 512, 50, 68) f32, rois: (2000,4) f32, roi_indices: (2000,) i32
// out: (2000, 512*7*7) f32
//
// Two-kernel scheme:
//   roi_prep: one thread per roi computes bin geometry (XLA-exact fp32:
//             divide-by-7 as multiply-by-fl(1/7)) into a packed 64B record.
//   roi_pool: one warp per (roi, 4 channels). Row loop does 4 coalesced loads
//             off one address register; per-pw reduce runs 4 channels in
//             parallel across lane groups. Span-tier templated (NR=1/2/3).

#define NC    512
#define FH    50
#define FW    68
#define PLANE (FH * FW)
#define PP    7
#define SCALE 0.0625f
#define NEG_INF (-CUDART_INF_F)

// packed per-roi record: 16 ints (64B). [0]=base(n*NC*PLANE + w0), [1]=span,
// [2]=maxw, [3..9] = hs | he<<8 | (ws-w0)<<16 | (we-w0)<<24
__device__ __align__(16) int g_rec[4096 * 16];

__global__ void roi_prep(const float* __restrict__ rois,
                         const int*   __restrict__ ridx, int R)
{
    int r = blockIdx.x * blockDim.x + threadIdx.x;
    if (r >= R) return;

    const float y1 = rois[r * 4 + 0];
    const float x1 = rois[r * 4 + 1];
    const float y2 = rois[r * 4 + 2];
    const float x2 = rois[r * 4 + 3];
    const float rb0 = rintf(__fmul_rn(x1, SCALE));
    const float rb1 = rintf(__fmul_rn(y1, SCALE));
    const float rb2 = rintf(__fmul_rn(x2, SCALE));
    const float rb3 = rintf(__fmul_rn(y2, SCALE));
    const float roiw = fmaxf(__fadd_rn(__fsub_rn(rb2, rb0), 1.0f), 1.0f);
    const float roih = fmaxf(__fadd_rn(__fsub_rn(rb3, rb1), 1.0f), 1.0f);
    const float R7 = (float)(1.0 / 7.0);          // XLA: x/7 -> x * fl(1/7)
    const float bw = __fmul_rn(roiw, R7);
    const float bh = __fmul_rn(roih, R7);

    const int w0 = (int)fminf(fmaxf(rb0, 0.0f), (float)FW);   // == ws[0]
    int maxw = 0;
    int pack[PP];
#pragma unroll
    for (int p = 0; p < PP; p++) {
        const float fp  = (float)p;
        const float fp1 = (float)(p + 1);
        int hs = (int)fminf(fmaxf(__fadd_rn(floorf(__fmul_rn(fp,  bh)), rb1), 0.0f), (float)FH);
        int he = (int)fminf(fmaxf(__fadd_rn(ceilf (__fmul_rn(fp1, bh)), rb1), 0.0f), (float)FH);
        int ws = (int)fminf(fmaxf(__fadd_rn(floorf(__fmul_rn(fp,  bw)), rb0), 0.0f), (float)FW);
        int we = (int)fminf(fmaxf(__fadd_rn(ceilf (__fmul_rn(fp1, bw)), rb0), 0.0f), (float)FW);
        maxw = max(maxw, we - ws);
        pack[p] = hs | (he << 8) | ((ws - w0) << 16) | ((we - w0) << 24);
    }
    const int span = ((pack[PP - 1] >> 24) & 0xff);   // we[6]-w0

    int* rec = g_rec + r * 16;
    rec[0] = ridx[r] * (NC * PLANE) + w0;
    rec[1] = span;
    rec[2] = maxw;
#pragma unroll
    for (int p = 0; p < PP; p++) rec[3 + p] = pack[p];
}

template <int NR>
__device__ __forceinline__ void pool_warp(const float* __restrict__ fm,
                                          int v, int span, int maxw, int lane,
                                          float* __restrict__ scol,
                                          float* __restrict__ sout)
{
    const int ch = lane >> 3;          // channel handled in reduce phase
    const int pw = lane & 7;           // pw bin handled in reduce phase
    const int mypk = __shfl_sync(0xffffffffu, v, 3 + (pw < PP ? pw : 0));
    const int j0 = (mypk >> 16) & 0xff;
    const int j1 = (mypk >> 24) & 0xff;

    bool act[NR];
#pragma unroll
    for (int q = 0; q < NR; q++) act[q] = (lane + q * 32) < span;

#pragma unroll
    for (int ph = 0; ph < PP; ph++) {
        const int pk = __shfl_sync(0xffffffffu, v, 3 + ph);
        const int h0 = pk & 0xff;
        const int h1 = (pk >> 8) & 0xff;

        float m[NR][4];
#pragma unroll
        for (int q = 0; q < NR; q++)
#pragma unroll
            for (int k = 0; k < 4; k++) m[q][k] = NEG_INF;

        const float* p = fm + h0 * FW;
        for (int h = h0; h < h1; h++) {
#pragma unroll
            for (int q = 0; q < NR; q++) {
                if (act[q]) {
#pragma unroll
                    for (int k = 0; k < 4; k++)
                        m[q][k] = fmaxf(m[q][k], __ldg(p + lane + q * 32 + k * PLANE));
                }
            }
            p += FW;
        }

        // column maxes -> smem: channel k at scol[k*97 + col]
#pragma unroll
        for (int k = 0; k < 4; k++)
#pragma unroll
            for (int q = 0; q < NR; q++)
                scol[k * 97 + q * 32 + lane] = m[q][k];
        __syncwarp();

        // 4-channel-parallel per-pw reduce
        float mm = NEG_INF;
        const float* s = scol + ch * 97;
        for (int k2 = 0; k2 < maxw; k2++) {
            const int j = j0 + k2;
            if (j < j1) mm = fmaxf(mm, s[j]);
        }
        if (pw < PP)
            sout[ch * 49 + ph * PP + pw] = (mm == NEG_INF) ? 0.0f : mm;
        __syncwarp();
    }
}

__global__ __launch_bounds__(256, 6)
void roi_pool(const float* __restrict__ x, float* __restrict__ out, int R)
{
    __shared__ float s_col[8][4 * 97];
    __shared__ float s_out[8][200];

    const int r    = blockIdx.x;
    const int warp = threadIdx.x >> 5;
    const int lane = threadIdx.x & 31;
    const int c0   = blockIdx.y * 32 + warp * 4;   // 16 * 32 = 512 channels

    int v = 0;
    if (lane < 16) v = g_rec[r * 16 + lane];
    const int base = __shfl_sync(0xffffffffu, v, 0);
    const int span = __shfl_sync(0xffffffffu, v, 1);
    const int maxw = __shfl_sync(0xffffffffu, v, 2);

    const float* fm   = x + base + c0 * PLANE;     // row 0, col w0, channel c0
    float*       scol = s_col[warp];
    float*       sout = s_out[warp];

    if (span <= 32)      pool_warp<1>(fm, v, span, maxw, lane, scol, sout);
    else if (span <= 64) pool_warp<2>(fm, v, span, maxw, lane, scol, sout);
    else                 pool_warp<3>(fm, v, span, maxw, lane, scol, sout);

    // 196 contiguous floats per warp
    const long long ob = (long long)r * (NC * 49) + (long long)c0 * 49;
#pragma unroll
    for (int i = 0; i < 7; i++) {
        const int idx = i * 32 + lane;
        if (idx < 196) out[ob + idx] = sout[idx];
    }
}

extern "C" void kernel_launch(void* const* d_in, const int* in_sizes, int n_in,
                              void* d_out, int out_size)
{
    const float* x    = (const float*)d_in[0];
    const float* rois = (const float*)d_in[1];
    const int*   ridx = (const int*)d_in[2];
    float*       out  = (float*)d_out;
    const int R = in_sizes[2];

    roi_prep<<<(R + 255) / 256, 256>>>(rois, ridx, R);
    dim3 grid(R, NC / 32);
    roi_pool<<<grid, 256>>>(x, out, R);
}